// round 13
// baseline (speedup 1.0000x reference)
#include <cuda_runtime.h>
#include <cuda_fp16.h>
#include <mma.h>
#include <cstdint>

using namespace nvcuda;

#define Nn 100000
#define Ee 3200000
#define F_IN 128
#define H1 64
#define H2 32
#define NC 10
#define SCAN_B 1024
#define NB_SCAN ((Nn + SCAN_B - 1) / SCAN_B)
#define FULLM 0xFFFFFFFFu

struct __align__(8) EdgeW { int s; float w; };

// ---- scratch (static device globals; no allocation) ----
__device__ int    g_is64;
__device__ int    d_deg[Nn];
__device__ int    d_rowptr[Nn];
__device__ float  d_dinv[Nn];
__device__ int    d_rank[Ee];               // rank of edge within its dst row
__device__ EdgeW  d_edges[Ee];              // CSR-sorted (src, norm)
__device__ int    d_blocksums[128];
__device__ __half d_h1[(size_t)Nn * H1];    // XW1 in fp16 (gather payload)
__device__ __half d_h2[(size_t)Nn * H2];    // layer-2 pre-agg in fp16

// ---------------------------------------------------------------------------
__global__ void k_zero_deg() {
    int i = blockIdx.x * blockDim.x + threadIdx.x;
    if (i < Nn) d_deg[i] = 0;
}

// Detect whether edge_index is int64 (odd 32-bit words all zero) or int32.
__global__ void k_detect(const int* __restrict__ ei) {
    int any = 0;
    for (int i = threadIdx.x; i < 128; i += 32)
        if (ei[2 * i + 1] != 0) any = 1;
    unsigned b = __ballot_sync(FULLM, any);
    if (threadIdx.x == 0) g_is64 = (b == 0) ? 1 : 0;
}

__device__ __forceinline__ int load_dst(const void* ei, int is64, int e) {
    if (is64) return (int)((const long long*)ei)[(size_t)Ee + e];
    return ((const int*)ei)[(size_t)Ee + e];
}
__device__ __forceinline__ int load_src(const void* ei, int is64, int e) {
    if (is64) return (int)((const long long*)ei)[e];
    return ((const int*)ei)[e];
}

// Histogram degrees on dst; the atomic's return value IS the edge's rank.
__global__ void k_deg(const void* __restrict__ ei) {
    int is64 = g_is64;
    int stride = gridDim.x * blockDim.x;
    for (int e = blockIdx.x * blockDim.x + threadIdx.x; e < Ee; e += stride) {
        d_rank[e] = atomicAdd(&d_deg[load_dst(ei, is64, e)], 1);
    }
}

// Block-level exclusive scan of deg (Hillis-Steele), block totals out.
__global__ void k_scan1() {
    __shared__ int sd[SCAN_B];
    int tid = threadIdx.x;
    int i = blockIdx.x * SCAN_B + tid;
    int v = (i < Nn) ? d_deg[i] : 0;
    sd[tid] = v;
    __syncthreads();
    #pragma unroll
    for (int off = 1; off < SCAN_B; off <<= 1) {
        int t = (tid >= off) ? sd[tid - off] : 0;
        __syncthreads();
        sd[tid] += t;
        __syncthreads();
    }
    if (i < Nn) d_rowptr[i] = sd[tid] - v;     // exclusive within block
    if (tid == SCAN_B - 1) d_blocksums[blockIdx.x] = sd[tid];
}

// Parallel exclusive scan of the 98 block sums (one 128-thread block).
__global__ void k_scan2() {
    __shared__ int sd[128];
    int tid = threadIdx.x;
    int v = (tid < NB_SCAN) ? d_blocksums[tid] : 0;
    sd[tid] = v;
    __syncthreads();
    #pragma unroll
    for (int off = 1; off < 128; off <<= 1) {
        int t = (tid >= off) ? sd[tid - off] : 0;
        __syncthreads();
        sd[tid] += t;
        __syncthreads();
    }
    if (tid < NB_SCAN) d_blocksums[tid] = sd[tid] - v;   // exclusive
}

__global__ void k_scan3() {
    int i = blockIdx.x * blockDim.x + threadIdx.x;
    if (i >= Nn) return;
    d_rowptr[i] += d_blocksums[i >> 10];
    d_dinv[i] = rsqrtf((float)d_deg[i] + 1.0f);
}

// Scatter edges into CSR slots — NO atomics (position = rowptr + rank).
__global__ void k_scatter(const void* __restrict__ ei) {
    int is64 = g_is64;
    int stride = gridDim.x * blockDim.x;
    for (int e = blockIdx.x * blockDim.x + threadIdx.x; e < Ee; e += stride) {
        int s = load_src(ei, is64, e);
        int d = load_dst(ei, is64, e);
        int p = d_rowptr[d] + d_rank[e];
        EdgeW ew;
        ew.s = s;
        ew.w = d_dinv[s] * d_dinv[d];
        d_edges[p] = ew;
    }
}

// ---------------------------------------------------------------------------
// GEMM1 via WMMA fp16 (HMMA), fp32 accumulate, fp16 epilogue.
// 64-row x 64-col block tile, K=128 fully staged. 8 warps x 2 fragments.
#define GA_PITCH 136   // half, 272B = 17x16B -> conflict-free, 16B-mult ldm
#define GB_PITCH 72    // half, 144B = 9x16B
__global__ __launch_bounds__(256) void k_gemm1(const float* __restrict__ X,
                                               const float* __restrict__ W1) {
    __shared__ __align__(16) char sm[64 * GA_PITCH * 2 + 128 * GB_PITCH * 2];
    __half* sA = (__half*)sm;                              // [64][GA_PITCH]
    __half* sB = (__half*)(sm + 64 * GA_PITCH * 2);        // [128][GB_PITCH]
    float*  sC = (float*)sm;                               // [64][64] (reuse)

    int tid = threadIdx.x;
    int row0 = blockIdx.x * 64;

    // stage X tile (64x128 fp32 -> fp16)
    #pragma unroll
    for (int it = 0; it < 8; it++) {
        int i4 = (it * 256 + tid) * 4;       // 0..8191 step 4
        int r = i4 >> 7, c = i4 & 127;
        int row = row0 + r;
        float4 v = make_float4(0.f, 0.f, 0.f, 0.f);
        if (row < Nn) v = *(const float4*)&X[(size_t)row * 128 + c];
        __half2* dst = (__half2*)&sA[r * GA_PITCH + c];
        dst[0] = __floats2half2_rn(v.x, v.y);
        dst[1] = __floats2half2_rn(v.z, v.w);
    }
    // stage W1 (128x64 fp32 -> fp16)
    #pragma unroll
    for (int it = 0; it < 8; it++) {
        int i4 = (it * 256 + tid) * 4;       // 0..8191 step 4
        int k = i4 >> 6, c = i4 & 63;
        float4 v = *(const float4*)&W1[(size_t)k * 64 + c];
        __half2* dst = (__half2*)&sB[k * GB_PITCH + c];
        dst[0] = __floats2half2_rn(v.x, v.y);
        dst[1] = __floats2half2_rn(v.z, v.w);
    }
    __syncthreads();

    int wid = tid >> 5;
    int ct = wid & 3;                        // col tile 0..3
    int rp = wid >> 2;                       // row pair 0..1

    wmma::fragment<wmma::accumulator, 16, 16, 16, float> acc0, acc1;
    wmma::fill_fragment(acc0, 0.0f);
    wmma::fill_fragment(acc1, 0.0f);
    wmma::fragment<wmma::matrix_a, 16, 16, 16, __half, wmma::row_major> a0, a1;
    wmma::fragment<wmma::matrix_b, 16, 16, 16, __half, wmma::row_major> b;

    #pragma unroll
    for (int kt = 0; kt < 8; kt++) {
        wmma::load_matrix_sync(b, &sB[kt * 16 * GB_PITCH + ct * 16], GB_PITCH);
        wmma::load_matrix_sync(a0, &sA[(rp * 32 + 0) * GA_PITCH + kt * 16], GA_PITCH);
        wmma::load_matrix_sync(a1, &sA[(rp * 32 + 16) * GA_PITCH + kt * 16], GA_PITCH);
        wmma::mma_sync(acc0, a0, b, acc0);
        wmma::mma_sync(acc1, a1, b, acc1);
    }
    __syncthreads();                         // all reads of sA done before reuse

    wmma::store_matrix_sync(&sC[(rp * 32 + 0) * 64 + ct * 16], acc0, 64,
                            wmma::mem_row_major);
    wmma::store_matrix_sync(&sC[(rp * 32 + 16) * 64 + ct * 16], acc1, 64,
                            wmma::mem_row_major);
    __syncthreads();

    // convert + coalesced fp16 store
    #pragma unroll
    for (int it = 0; it < 4; it++) {
        int i4 = (it * 256 + tid) * 4;       // 0..4095 step 4
        int r = i4 >> 6, c = i4 & 63;
        int row = row0 + r;
        if (row < Nn) {
            float4 v = *(const float4*)&sC[r * 64 + c];
            __half2* dst = (__half2*)&d_h1[(size_t)row * 64 + c];
            dst[0] = __floats2half2_rn(v.x, v.y);
            dst[1] = __floats2half2_rn(v.z, v.w);
        }
    }
}

// Aggregation layer 1 + self-loop + bias + ReLU + FUSED GEMM2 (64x32 GEMV).
// After the xor-16 reduce every lane holds the full 4-feature sums, so the
// warp finishes h2[n] = relu(out1[n]) @ W2 in-register: lane owns output
// column `lane`; features broadcast via shfl; sW2 reads conflict-free.
__global__ __launch_bounds__(256) void k_agg1(const float* __restrict__ b1,
                                              const float* __restrict__ W2) {
    __shared__ float sW2[64 * 32];      // 8 KB
    int tid = threadIdx.x;
    for (int i = tid; i < 64 * 32; i += 256) sW2[i] = W2[i];
    __syncthreads();

    int warp = (blockIdx.x * blockDim.x + tid) >> 5;
    int lane = tid & 31;
    if (warp >= Nn) return;
    int n = warp;
    int start = d_rowptr[n];
    int end = start + d_deg[n];
    int half = lane >> 4;               // which edge of the pair
    int sub  = lane & 15;               // feature group (4 halves each)
    const __half* __restrict__ h = d_h1;
    float a0 = 0.f, a1 = 0.f, a2 = 0.f, a3 = 0.f;

    for (int base = start; base < end; base += 32) {
        int rem = end - base; if (rem > 32) rem = 32;
        int s_l = 0; float w_l = 0.f;
        if (lane < rem) { EdgeW ew = d_edges[base + lane]; s_l = ew.s; w_l = ew.w; }
        int npair = (rem + 1) >> 1;
        for (int p = 0; p < npair; p++) {
            int idx = 2 * p + half;
            int   s = __shfl_sync(FULLM, s_l, idx);
            float w = __shfl_sync(FULLM, w_l, idx);
            if (idx < rem) {
                uint2 raw = *(const uint2*)(h + (size_t)s * 64 + sub * 4);
                float2 lo = __half22float2(*(__half2*)&raw.x);
                float2 hi = __half22float2(*(__half2*)&raw.y);
                a0 += lo.x * w; a1 += lo.y * w; a2 += hi.x * w; a3 += hi.y * w;
            }
        }
    }
    a0 += __shfl_xor_sync(FULLM, a0, 16);
    a1 += __shfl_xor_sync(FULLM, a1, 16);
    a2 += __shfl_xor_sync(FULLM, a2, 16);
    a3 += __shfl_xor_sync(FULLM, a3, 16);

    // self-loop + bias + relu on ALL lanes (duplicated across halves)
    float di = d_dinv[n];
    float sl = di * di;
    uint2 raw = *(const uint2*)(h + (size_t)n * 64 + sub * 4);
    float2 lo = __half22float2(*(__half2*)&raw.x);
    float2 hi = __half22float2(*(__half2*)&raw.y);
    a0 += lo.x * sl; a1 += lo.y * sl; a2 += hi.x * sl; a3 += hi.y * sl;
    float4 bb = ((const float4*)b1)[sub];
    float v0 = fmaxf(a0 + bb.x, 0.f);
    float v1 = fmaxf(a1 + bb.y, 0.f);
    float v2 = fmaxf(a2 + bb.z, 0.f);
    float v3 = fmaxf(a3 + bb.w, 0.f);

    // fused GEMV: p = sum_f v_f * W2[f][lane]
    float p = 0.f;
    #pragma unroll
    for (int f16 = 0; f16 < 16; f16++) {
        float u0 = __shfl_sync(FULLM, v0, f16);
        float u1 = __shfl_sync(FULLM, v1, f16);
        float u2 = __shfl_sync(FULLM, v2, f16);
        float u3 = __shfl_sync(FULLM, v3, f16);
        p += u0 * sW2[(f16 * 4 + 0) * 32 + lane];
        p += u1 * sW2[(f16 * 4 + 1) * 32 + lane];
        p += u2 * sW2[(f16 * 4 + 2) * 32 + lane];
        p += u3 * sW2[(f16 * 4 + 3) * 32 + lane];
    }
    d_h2[(size_t)n * 32 + lane] = __float2half_rn(p);
}

// Aggregation layer 2 + bias + ReLU + classifier GEMV + log_softmax (warp/node)
__global__ __launch_bounds__(256) void k_final(const float* __restrict__ b2,
                                               const float* __restrict__ Wc,
                                               const float* __restrict__ bc,
                                               float* __restrict__ out) {
    __shared__ float sWc[32 * NC];
    __shared__ float sb2[32];
    __shared__ float sbc[16];
    int tid = threadIdx.x;
    for (int i = tid; i < 32 * NC; i += 256) sWc[i] = Wc[i];
    if (tid < 32) sb2[tid] = b2[tid];
    if (tid < NC) sbc[tid] = bc[tid];
    __syncthreads();

    int warp = (blockIdx.x * blockDim.x + tid) >> 5;
    int lane = tid & 31;
    if (warp >= Nn) return;
    int n = warp;
    int start = d_rowptr[n];
    int end = start + d_deg[n];
    int grp = lane >> 3;                // which of 4 edges
    int sub = lane & 7;                 // feature group (4 halves each)
    const __half* __restrict__ h = d_h2;
    float a0 = 0.f, a1 = 0.f, a2 = 0.f, a3 = 0.f;

    for (int base = start; base < end; base += 32) {
        int rem = end - base; if (rem > 32) rem = 32;
        int s_l = 0; float w_l = 0.f;
        if (lane < rem) { EdgeW ew = d_edges[base + lane]; s_l = ew.s; w_l = ew.w; }
        int ngrp = (rem + 3) >> 2;
        for (int p = 0; p < ngrp; p++) {
            int idx = 4 * p + grp;
            int   s = __shfl_sync(FULLM, s_l, idx);
            float w = __shfl_sync(FULLM, w_l, idx);
            if (idx < rem) {
                uint2 raw = *(const uint2*)(h + (size_t)s * 32 + sub * 4);
                float2 lo = __half22float2(*(__half2*)&raw.x);
                float2 hi = __half22float2(*(__half2*)&raw.y);
                a0 += lo.x * w; a1 += lo.y * w; a2 += hi.x * w; a3 += hi.y * w;
            }
        }
    }
    a0 += __shfl_xor_sync(FULLM, a0, 8);  a0 += __shfl_xor_sync(FULLM, a0, 16);
    a1 += __shfl_xor_sync(FULLM, a1, 8);  a1 += __shfl_xor_sync(FULLM, a1, 16);
    a2 += __shfl_xor_sync(FULLM, a2, 8);  a2 += __shfl_xor_sync(FULLM, a2, 16);
    a3 += __shfl_xor_sync(FULLM, a3, 8);  a3 += __shfl_xor_sync(FULLM, a3, 16);

    float di = d_dinv[n];
    float sl = di * di;
    uint2 raw = *(const uint2*)(h + (size_t)n * 32 + sub * 4);
    float2 lo = __half22float2(*(__half2*)&raw.x);
    float2 hi = __half22float2(*(__half2*)&raw.y);
    a0 += lo.x * sl; a1 += lo.y * sl; a2 += hi.x * sl; a3 += hi.y * sl;
    float v0 = fmaxf(a0 + sb2[sub * 4 + 0], 0.f);
    float v1 = fmaxf(a1 + sb2[sub * 4 + 1], 0.f);
    float v2 = fmaxf(a2 + sb2[sub * 4 + 2], 0.f);
    float v3 = fmaxf(a3 + sb2[sub * 4 + 3], 0.f);

    float p[NC];
    #pragma unroll
    for (int c = 0; c < NC; c++) {
        p[c] = v0 * sWc[(sub * 4 + 0) * NC + c]
             + v1 * sWc[(sub * 4 + 1) * NC + c]
             + v2 * sWc[(sub * 4 + 2) * NC + c]
             + v3 * sWc[(sub * 4 + 3) * NC + c];
    }
    #pragma unroll
    for (int off = 4; off >= 1; off >>= 1) {
        #pragma unroll
        for (int c = 0; c < NC; c++)
            p[c] += __shfl_xor_sync(FULLM, p[c], off);
    }
    if (lane == 0) {
        #pragma unroll
        for (int c = 0; c < NC; c++) p[c] += sbc[c];
        float m = p[0];
        #pragma unroll
        for (int c = 1; c < NC; c++) m = fmaxf(m, p[c]);
        float s = 0.f;
        #pragma unroll
        for (int c = 0; c < NC; c++) s += expf(p[c] - m);
        float lse = m + logf(s);
        #pragma unroll
        for (int c = 0; c < NC; c++)
            out[(size_t)n * NC + c] = p[c] - lse;
    }
}

// ---------------------------------------------------------------------------
extern "C" void kernel_launch(void* const* d_in, const int* in_sizes, int n_in,
                              void* d_out, int out_size) {
    const float* x  = (const float*)d_in[0];
    const void*  ei = d_in[1];
    const float* W1 = (const float*)d_in[2];
    const float* b1 = (const float*)d_in[3];
    const float* W2 = (const float*)d_in[4];
    const float* b2 = (const float*)d_in[5];
    const float* Wc = (const float*)d_in[6];
    const float* bc = (const float*)d_in[7];
    float* out = (float*)d_out;

    k_zero_deg<<<(Nn + 255) / 256, 256>>>();
    k_detect<<<1, 32>>>((const int*)ei);
    k_deg<<<(Ee + 255) / 256, 256>>>(ei);
    // gemm1 stays at launch #3 so the ncu window keeps capturing it.
    k_gemm1<<<(Nn + 63) / 64, 256>>>(x, W1);
    k_scan1<<<NB_SCAN, SCAN_B>>>();
    k_scan2<<<1, 128>>>();
    k_scan3<<<(Nn + 255) / 256, 256>>>();
    k_scatter<<<(Ee + 255) / 256, 256>>>(ei);

    k_agg1<<<(Nn + 7) / 8, 256>>>(b1, W2);   // fused agg1 + gemm2
    k_final<<<(Nn + 7) / 8, 256>>>(b2, Wc, bc, out);
}

// round 16
// speedup vs baseline: 1.0896x; 1.0896x over previous
#include <cuda_runtime.h>
#include <cuda_fp16.h>
#include <mma.h>
#include <cstdint>

using namespace nvcuda;

#define Nn 100000
#define Ee 3200000
#define F_IN 128
#define H1 64
#define H2 32
#define NC 10
#define SCAN_B 1024
#define NB_SCAN ((Nn + SCAN_B - 1) / SCAN_B)
#define FULLM 0xFFFFFFFFu

struct __align__(8) EdgeW { int s; float w; };

// ---- scratch (static device globals; no allocation) ----
__device__ int    g_is64;
__device__ int    d_deg[Nn];
__device__ int    d_rowptr[Nn];
__device__ float  d_dinv[Nn];
__device__ int    d_rank[Ee];               // rank of edge within its dst row
__device__ EdgeW  d_edges[Ee];              // CSR-sorted (src, norm)
__device__ int    d_blocksums[128];
__device__ __half d_h1[(size_t)Nn * H1];    // XW1 in fp16 (gather payload)
__device__ float  d_out1[(size_t)Nn * H1];  // post-agg1 (fp32, GEMM2 input)
__device__ __half d_h2[(size_t)Nn * H2];    // out1W2 in fp16 (gather payload)

// ---------------------------------------------------------------------------
__global__ void k_zero_deg() {
    int i = blockIdx.x * blockDim.x + threadIdx.x;
    if (i < Nn) d_deg[i] = 0;
}

// Detect whether edge_index is int64 (odd 32-bit words all zero) or int32.
__global__ void k_detect(const int* __restrict__ ei) {
    int any = 0;
    for (int i = threadIdx.x; i < 128; i += 32)
        if (ei[2 * i + 1] != 0) any = 1;
    unsigned b = __ballot_sync(FULLM, any);
    if (threadIdx.x == 0) g_is64 = (b == 0) ? 1 : 0;
}

// Histogram degrees on dst, 4 edges/thread (vectorized); atomic return = rank.
__global__ void k_deg(const void* __restrict__ ei) {
    int is64 = g_is64;
    int t = blockIdx.x * blockDim.x + threadIdx.x;
    int e = t * 4;
    if (e >= Ee) return;
    int d0, d1, d2, d3;
    if (is64) {
        const longlong2* p = (const longlong2*)((const long long*)ei + Ee);
        longlong2 a = p[t * 2], b = p[t * 2 + 1];
        d0 = (int)a.x; d1 = (int)a.y; d2 = (int)b.x; d3 = (int)b.y;
    } else {
        int4 v = ((const int4*)((const int*)ei + Ee))[t];
        d0 = v.x; d1 = v.y; d2 = v.z; d3 = v.w;
    }
    int4 r;
    r.x = atomicAdd(&d_deg[d0], 1);
    r.y = atomicAdd(&d_deg[d1], 1);
    r.z = atomicAdd(&d_deg[d2], 1);
    r.w = atomicAdd(&d_deg[d3], 1);
    ((int4*)d_rank)[t] = r;
}

// Block-level exclusive scan of deg (Hillis-Steele), block totals out.
__global__ void k_scan1() {
    __shared__ int sd[SCAN_B];
    int tid = threadIdx.x;
    int i = blockIdx.x * SCAN_B + tid;
    int v = (i < Nn) ? d_deg[i] : 0;
    sd[tid] = v;
    __syncthreads();
    #pragma unroll
    for (int off = 1; off < SCAN_B; off <<= 1) {
        int t = (tid >= off) ? sd[tid - off] : 0;
        __syncthreads();
        sd[tid] += t;
        __syncthreads();
    }
    if (i < Nn) d_rowptr[i] = sd[tid] - v;     // exclusive within block
    if (tid == SCAN_B - 1) d_blocksums[blockIdx.x] = sd[tid];
}

// Parallel exclusive scan of the 98 block sums (one 128-thread block).
__global__ void k_scan2() {
    __shared__ int sd[128];
    int tid = threadIdx.x;
    int v = (tid < NB_SCAN) ? d_blocksums[tid] : 0;
    sd[tid] = v;
    __syncthreads();
    #pragma unroll
    for (int off = 1; off < 128; off <<= 1) {
        int t = (tid >= off) ? sd[tid - off] : 0;
        __syncthreads();
        sd[tid] += t;
        __syncthreads();
    }
    if (tid < NB_SCAN) d_blocksums[tid] = sd[tid] - v;   // exclusive
}

__global__ void k_scan3() {
    int i = blockIdx.x * blockDim.x + threadIdx.x;
    if (i >= Nn) return;
    d_rowptr[i] += d_blocksums[i >> 10];
    d_dinv[i] = rsqrtf((float)d_deg[i] + 1.0f);
}

// Scatter edges into CSR slots, 4 edges/thread — NO atomics.
__global__ void k_scatter(const void* __restrict__ ei) {
    int is64 = g_is64;
    int t = blockIdx.x * blockDim.x + threadIdx.x;
    int e = t * 4;
    if (e >= Ee) return;
    int s0, s1, s2, s3, d0, d1, d2, d3;
    if (is64) {
        const longlong2* ps = (const longlong2*)ei;
        const longlong2* pd = (const longlong2*)((const long long*)ei + Ee);
        longlong2 a = ps[t * 2], b = ps[t * 2 + 1];
        longlong2 c = pd[t * 2], d = pd[t * 2 + 1];
        s0 = (int)a.x; s1 = (int)a.y; s2 = (int)b.x; s3 = (int)b.y;
        d0 = (int)c.x; d1 = (int)c.y; d2 = (int)d.x; d3 = (int)d.y;
    } else {
        int4 vs = ((const int4*)ei)[t];
        int4 vd = ((const int4*)((const int*)ei + Ee))[t];
        s0 = vs.x; s1 = vs.y; s2 = vs.z; s3 = vs.w;
        d0 = vd.x; d1 = vd.y; d2 = vd.z; d3 = vd.w;
    }
    int4 r = ((const int4*)d_rank)[t];
    EdgeW ew;
    ew.s = s0; ew.w = d_dinv[s0] * d_dinv[d0]; d_edges[d_rowptr[d0] + r.x] = ew;
    ew.s = s1; ew.w = d_dinv[s1] * d_dinv[d1]; d_edges[d_rowptr[d1] + r.y] = ew;
    ew.s = s2; ew.w = d_dinv[s2] * d_dinv[d2]; d_edges[d_rowptr[d2] + r.z] = ew;
    ew.s = s3; ew.w = d_dinv[s3] * d_dinv[d3]; d_edges[d_rowptr[d3] + r.w] = ew;
}

// ---------------------------------------------------------------------------
// GEMM1 via WMMA fp16 (HMMA), fp32 accumulate, fp16 epilogue.
// 64-row x 64-col block tile, K=128 fully staged. 8 warps x 2 fragments.
#define GA_PITCH 136   // half, 272B = 17x16B -> conflict-free, 16B-mult ldm
#define GB_PITCH 72    // half, 144B = 9x16B
__global__ __launch_bounds__(256) void k_gemm1(const float* __restrict__ X,
                                               const float* __restrict__ W1) {
    __shared__ __align__(16) char sm[64 * GA_PITCH * 2 + 128 * GB_PITCH * 2];
    __half* sA = (__half*)sm;                              // [64][GA_PITCH]
    __half* sB = (__half*)(sm + 64 * GA_PITCH * 2);        // [128][GB_PITCH]
    float*  sC = (float*)sm;                               // [64][64] (reuse)

    int tid = threadIdx.x;
    int row0 = blockIdx.x * 64;

    // stage X tile (64x128 fp32 -> fp16)
    #pragma unroll
    for (int it = 0; it < 8; it++) {
        int i4 = (it * 256 + tid) * 4;       // 0..8191 step 4
        int r = i4 >> 7, c = i4 & 127;
        int row = row0 + r;
        float4 v = make_float4(0.f, 0.f, 0.f, 0.f);
        if (row < Nn) v = *(const float4*)&X[(size_t)row * 128 + c];
        __half2* dst = (__half2*)&sA[r * GA_PITCH + c];
        dst[0] = __floats2half2_rn(v.x, v.y);
        dst[1] = __floats2half2_rn(v.z, v.w);
    }
    // stage W1 (128x64 fp32 -> fp16)
    #pragma unroll
    for (int it = 0; it < 8; it++) {
        int i4 = (it * 256 + tid) * 4;       // 0..8191 step 4
        int k = i4 >> 6, c = i4 & 63;
        float4 v = *(const float4*)&W1[(size_t)k * 64 + c];
        __half2* dst = (__half2*)&sB[k * GB_PITCH + c];
        dst[0] = __floats2half2_rn(v.x, v.y);
        dst[1] = __floats2half2_rn(v.z, v.w);
    }
    __syncthreads();

    int wid = tid >> 5;
    int ct = wid & 3;                        // col tile 0..3
    int rp = wid >> 2;                       // row pair 0..1

    wmma::fragment<wmma::accumulator, 16, 16, 16, float> acc0, acc1;
    wmma::fill_fragment(acc0, 0.0f);
    wmma::fill_fragment(acc1, 0.0f);
    wmma::fragment<wmma::matrix_a, 16, 16, 16, __half, wmma::row_major> a0, a1;
    wmma::fragment<wmma::matrix_b, 16, 16, 16, __half, wmma::row_major> b;

    #pragma unroll
    for (int kt = 0; kt < 8; kt++) {
        wmma::load_matrix_sync(b, &sB[kt * 16 * GB_PITCH + ct * 16], GB_PITCH);
        wmma::load_matrix_sync(a0, &sA[(rp * 32 + 0) * GA_PITCH + kt * 16], GA_PITCH);
        wmma::load_matrix_sync(a1, &sA[(rp * 32 + 16) * GA_PITCH + kt * 16], GA_PITCH);
        wmma::mma_sync(acc0, a0, b, acc0);
        wmma::mma_sync(acc1, a1, b, acc1);
    }
    __syncthreads();                         // all reads of sA done before reuse

    wmma::store_matrix_sync(&sC[(rp * 32 + 0) * 64 + ct * 16], acc0, 64,
                            wmma::mem_row_major);
    wmma::store_matrix_sync(&sC[(rp * 32 + 16) * 64 + ct * 16], acc1, 64,
                            wmma::mem_row_major);
    __syncthreads();

    // convert + coalesced fp16 store
    #pragma unroll
    for (int it = 0; it < 4; it++) {
        int i4 = (it * 256 + tid) * 4;       // 0..4095 step 4
        int r = i4 >> 6, c = i4 & 63;
        int row = row0 + r;
        if (row < Nn) {
            float4 v = *(const float4*)&sC[r * 64 + c];
            __half2* dst = (__half2*)&d_h1[(size_t)row * 64 + c];
            dst[0] = __floats2half2_rn(v.x, v.y);
            dst[1] = __floats2half2_rn(v.z, v.w);
        }
    }
}

// Aggregation layer 1 (warp per node) + self-loop + bias + ReLU -> d_out1
// 16 lanes x 8B cover one 128B row -> 2 edges per gather LDG.
__global__ __launch_bounds__(256) void k_agg1(const float* __restrict__ b1) {
    int warp = (blockIdx.x * blockDim.x + threadIdx.x) >> 5;
    int lane = threadIdx.x & 31;
    if (warp >= Nn) return;
    int n = warp;
    int start = d_rowptr[n];
    int end = start + d_deg[n];
    int half = lane >> 4;               // which edge of the pair
    int sub  = lane & 15;               // feature group (4 halves each)
    const __half* __restrict__ h = d_h1;
    float a0 = 0.f, a1 = 0.f, a2 = 0.f, a3 = 0.f;

    for (int base = start; base < end; base += 32) {
        int rem = end - base; if (rem > 32) rem = 32;
        int s_l = 0; float w_l = 0.f;
        if (lane < rem) { EdgeW ew = d_edges[base + lane]; s_l = ew.s; w_l = ew.w; }
        int npair = (rem + 1) >> 1;
        for (int p = 0; p < npair; p++) {
            int idx = 2 * p + half;
            int   s = __shfl_sync(FULLM, s_l, idx);
            float w = __shfl_sync(FULLM, w_l, idx);
            if (idx < rem) {
                uint2 raw = *(const uint2*)(h + (size_t)s * 64 + sub * 4);
                float2 lo = __half22float2(*(__half2*)&raw.x);
                float2 hi = __half22float2(*(__half2*)&raw.y);
                a0 += lo.x * w; a1 += lo.y * w; a2 += hi.x * w; a3 += hi.y * w;
            }
        }
    }
    a0 += __shfl_xor_sync(FULLM, a0, 16);
    a1 += __shfl_xor_sync(FULLM, a1, 16);
    a2 += __shfl_xor_sync(FULLM, a2, 16);
    a3 += __shfl_xor_sync(FULLM, a3, 16);

    if (half == 0) {
        float di = d_dinv[n];
        float sl = di * di;
        uint2 raw = *(const uint2*)(h + (size_t)n * 64 + sub * 4);
        float2 lo = __half22float2(*(__half2*)&raw.x);
        float2 hi = __half22float2(*(__half2*)&raw.y);
        a0 += lo.x * sl; a1 += lo.y * sl; a2 += hi.x * sl; a3 += hi.y * sl;
        float4 bb = ((const float4*)b1)[sub];
        float4 o;
        o.x = fmaxf(a0 + bb.x, 0.f);
        o.y = fmaxf(a1 + bb.y, 0.f);
        o.z = fmaxf(a2 + bb.z, 0.f);
        o.w = fmaxf(a3 + bb.w, 0.f);
        ((float4*)d_out1)[(size_t)n * 16 + sub] = o;
    }
}

// GEMM2: h2[N,32] = out1[N,64] @ W2[64,32], epilogue stores fp16.
__global__ __launch_bounds__(256) void k_gemm2(const float* __restrict__ W2) {
    __shared__ float sW[64 * 32];
    __shared__ float sX[64 * 132];      // xT: [k][r], pitch 132
    int tid = threadIdx.x;
    int row0 = blockIdx.x * 128;
    int cidx = tid & 7;                 // c0 = cidx*4
    int ridx = tid >> 3;                // r0 = ridx*4 (0..124)
    float acc[4][4] = {};

    for (int i = tid; i < 64 * 32; i += 256) sW[i] = W2[i];
    for (int i = tid; i < 128 * 64; i += 256) {
        int r = i >> 6, k = i & 63;
        int row = row0 + r;
        sX[k * 132 + r] = (row < Nn) ? d_out1[(size_t)row * 64 + k] : 0.f;
    }
    __syncthreads();
    #pragma unroll
    for (int k = 0; k < 64; k++) {
        float4 w = *(const float4*)&sW[k * 32 + cidx * 4];
        float4 x = *(const float4*)&sX[k * 132 + ridx * 4];
        acc[0][0] += x.x * w.x; acc[0][1] += x.x * w.y; acc[0][2] += x.x * w.z; acc[0][3] += x.x * w.w;
        acc[1][0] += x.y * w.x; acc[1][1] += x.y * w.y; acc[1][2] += x.y * w.z; acc[1][3] += x.y * w.w;
        acc[2][0] += x.z * w.x; acc[2][1] += x.z * w.y; acc[2][2] += x.z * w.z; acc[2][3] += x.z * w.w;
        acc[3][0] += x.w * w.x; acc[3][1] += x.w * w.y; acc[3][2] += x.w * w.z; acc[3][3] += x.w * w.w;
    }
    #pragma unroll
    for (int rr = 0; rr < 4; rr++) {
        int row = row0 + ridx * 4 + rr;
        if (row < Nn) {
            __half2 p0 = __floats2half2_rn(acc[rr][0], acc[rr][1]);
            __half2 p1 = __floats2half2_rn(acc[rr][2], acc[rr][3]);
            __half2* dst = (__half2*)&d_h2[(size_t)row * 32 + cidx * 4];
            dst[0] = p0;
            dst[1] = p1;
        }
    }
}

// Aggregation layer 2 + bias + ReLU + classifier GEMV + log_softmax (warp/node)
__global__ __launch_bounds__(256) void k_final(const float* __restrict__ b2,
                                               const float* __restrict__ Wc,
                                               const float* __restrict__ bc,
                                               float* __restrict__ out) {
    __shared__ float sWc[32 * NC];
    __shared__ float sb2[32];
    __shared__ float sbc[16];
    int tid = threadIdx.x;
    for (int i = tid; i < 32 * NC; i += 256) sWc[i] = Wc[i];
    if (tid < 32) sb2[tid] = b2[tid];
    if (tid < NC) sbc[tid] = bc[tid];
    __syncthreads();

    int warp = (blockIdx.x * blockDim.x + tid) >> 5;
    int lane = tid & 31;
    if (warp >= Nn) return;
    int n = warp;
    int start = d_rowptr[n];
    int end = start + d_deg[n];
    int grp = lane >> 3;                // which of 4 edges
    int sub = lane & 7;                 // feature group (4 halves each)
    const __half* __restrict__ h = d_h2;
    float a0 = 0.f, a1 = 0.f, a2 = 0.f, a3 = 0.f;

    for (int base = start; base < end; base += 32) {
        int rem = end - base; if (rem > 32) rem = 32;
        int s_l = 0; float w_l = 0.f;
        if (lane < rem) { EdgeW ew = d_edges[base + lane]; s_l = ew.s; w_l = ew.w; }
        int ngrp = (rem + 3) >> 2;
        for (int p = 0; p < ngrp; p++) {
            int idx = 4 * p + grp;
            int   s = __shfl_sync(FULLM, s_l, idx);
            float w = __shfl_sync(FULLM, w_l, idx);
            if (idx < rem) {
                uint2 raw = *(const uint2*)(h + (size_t)s * 32 + sub * 4);
                float2 lo = __half22float2(*(__half2*)&raw.x);
                float2 hi = __half22float2(*(__half2*)&raw.y);
                a0 += lo.x * w; a1 += lo.y * w; a2 += hi.x * w; a3 += hi.y * w;
            }
        }
    }
    a0 += __shfl_xor_sync(FULLM, a0, 8);  a0 += __shfl_xor_sync(FULLM, a0, 16);
    a1 += __shfl_xor_sync(FULLM, a1, 8);  a1 += __shfl_xor_sync(FULLM, a1, 16);
    a2 += __shfl_xor_sync(FULLM, a2, 8);  a2 += __shfl_xor_sync(FULLM, a2, 16);
    a3 += __shfl_xor_sync(FULLM, a3, 8);  a3 += __shfl_xor_sync(FULLM, a3, 16);

    float di = d_dinv[n];
    float sl = di * di;
    uint2 raw = *(const uint2*)(h + (size_t)n * 32 + sub * 4);
    float2 lo = __half22float2(*(__half2*)&raw.x);
    float2 hi = __half22float2(*(__half2*)&raw.y);
    a0 += lo.x * sl; a1 += lo.y * sl; a2 += hi.x * sl; a3 += hi.y * sl;
    float v0 = fmaxf(a0 + sb2[sub * 4 + 0], 0.f);
    float v1 = fmaxf(a1 + sb2[sub * 4 + 1], 0.f);
    float v2 = fmaxf(a2 + sb2[sub * 4 + 2], 0.f);
    float v3 = fmaxf(a3 + sb2[sub * 4 + 3], 0.f);

    float p[NC];
    #pragma unroll
    for (int c = 0; c < NC; c++) {
        p[c] = v0 * sWc[(sub * 4 + 0) * NC + c]
             + v1 * sWc[(sub * 4 + 1) * NC + c]
             + v2 * sWc[(sub * 4 + 2) * NC + c]
             + v3 * sWc[(sub * 4 + 3) * NC + c];
    }
    #pragma unroll
    for (int off = 4; off >= 1; off >>= 1) {
        #pragma unroll
        for (int c = 0; c < NC; c++)
            p[c] += __shfl_xor_sync(FULLM, p[c], off);
    }
    if (lane == 0) {
        #pragma unroll
        for (int c = 0; c < NC; c++) p[c] += sbc[c];
        float m = p[0];
        #pragma unroll
        for (int c = 1; c < NC; c++) m = fmaxf(m, p[c]);
        float s = 0.f;
        #pragma unroll
        for (int c = 0; c < NC; c++) s += expf(p[c] - m);
        float lse = m + logf(s);
        #pragma unroll
        for (int c = 0; c < NC; c++)
            out[(size_t)n * NC + c] = p[c] - lse;
    }
}

// ---------------------------------------------------------------------------
extern "C" void kernel_launch(void* const* d_in, const int* in_sizes, int n_in,
                              void* d_out, int out_size) {
    const float* x  = (const float*)d_in[0];
    const void*  ei = d_in[1];
    const float* W1 = (const float*)d_in[2];
    const float* b1 = (const float*)d_in[3];
    const float* W2 = (const float*)d_in[4];
    const float* b2 = (const float*)d_in[5];
    const float* Wc = (const float*)d_in[6];
    const float* bc = (const float*)d_in[7];
    float* out = (float*)d_out;

    k_zero_deg<<<(Nn + 255) / 256, 256>>>();
    k_detect<<<1, 32>>>((const int*)ei);
    // gemm1 at #2 (independent); k_deg at #3 so the ncu window profiles it.
    k_gemm1<<<(Nn + 63) / 64, 256>>>(x, W1);
    k_deg<<<(Ee / 4 + 255) / 256, 256>>>(ei);
    k_scan1<<<NB_SCAN, SCAN_B>>>();
    k_scan2<<<1, 128>>>();
    k_scan3<<<(Nn + 255) / 256, 256>>>();
    k_scatter<<<(Ee / 4 + 255) / 256, 256>>>(ei);

    k_agg1<<<(Nn + 7) / 8, 256>>>(b1);
    k_gemm2<<<(Nn + 127) / 128, 256>>>(W2);
    k_final<<<(Nn + 7) / 8, 256>>>(b2, Wc, bc, out);
}

// round 17
// speedup vs baseline: 1.1177x; 1.0258x over previous
#include <cuda_runtime.h>
#include <cuda_fp16.h>
#include <mma.h>
#include <cstdint>

using namespace nvcuda;

#define Nn 100000
#define Ee 3200000
#define F_IN 128
#define H1 64
#define H2 32
#define NC 10
#define SCAN_B 1024
#define NB_SCAN ((Nn + SCAN_B - 1) / SCAN_B)
#define FULLM 0xFFFFFFFFu

struct __align__(8) EdgeW   { int s; float w; };
struct __align__(8) NodeInfo { int rp; float dinv; };

// ---- scratch (static device globals; no allocation) ----
__device__ int      g_is64;
__device__ int      d_deg[Nn];
__device__ int      d_rowptr[Nn];
__device__ float    d_dinv[Nn];
__device__ NodeInfo d_ninfo[Nn];
__device__ unsigned long long g_scanstate[NB_SCAN]; // hi32 status(1=agg,2=pfx), lo32 value
__device__ int      d_rank[Ee];             // rank of edge within its dst row
__device__ EdgeW    d_edges[Ee];            // CSR-sorted (src, norm)
__device__ __half   d_h1[(size_t)Nn * H1];  // XW1 in fp16 (gather payload)
__device__ float    d_out1[(size_t)Nn * H1];// post-agg1 (fp32, GEMM2 input)
__device__ __half   d_h2[(size_t)Nn * H2];  // out1W2 in fp16 (gather payload)

// ---------------------------------------------------------------------------
// init: zero deg + scan state, and detect edge_index dtype (warp 0 of block 0)
__global__ void k_init(const int* __restrict__ ei) {
    int i = blockIdx.x * blockDim.x + threadIdx.x;
    if (i < Nn) d_deg[i] = 0;
    if (i < NB_SCAN) g_scanstate[i] = 0ULL;
    if (blockIdx.x == 0 && threadIdx.x < 32) {
        int any = 0;
        for (int k = threadIdx.x; k < 128; k += 32)
            if (ei[2 * k + 1] != 0) any = 1;
        unsigned b = __ballot_sync(FULLM, any);
        if (threadIdx.x == 0) g_is64 = (b == 0) ? 1 : 0;
    }
}

// Histogram degrees on dst, 4 edges/thread (vectorized); atomic return = rank.
__global__ void k_deg(const void* __restrict__ ei) {
    int is64 = g_is64;
    int t = blockIdx.x * blockDim.x + threadIdx.x;
    int e = t * 4;
    if (e >= Ee) return;
    int d0, d1, d2, d3;
    if (is64) {
        const longlong2* p = (const longlong2*)((const long long*)ei + Ee);
        longlong2 a = p[t * 2], b = p[t * 2 + 1];
        d0 = (int)a.x; d1 = (int)a.y; d2 = (int)b.x; d3 = (int)b.y;
    } else {
        int4 v = ((const int4*)((const int*)ei + Ee))[t];
        d0 = v.x; d1 = v.y; d2 = v.z; d3 = v.w;
    }
    int4 r;
    r.x = atomicAdd(&d_deg[d0], 1);
    r.y = atomicAdd(&d_deg[d1], 1);
    r.z = atomicAdd(&d_deg[d2], 1);
    r.w = atomicAdd(&d_deg[d3], 1);
    ((int4*)d_rank)[t] = r;
}

// Single-launch decoupled-lookback exclusive scan of deg -> rowptr/ninfo/dinv.
// 98 blocks (all co-resident on 148 SMs -> lookback cannot deadlock).
__global__ __launch_bounds__(SCAN_B) void k_scan() {
    __shared__ int warpsum[32];
    __shared__ int s_base;
    int tid = threadIdx.x, b = blockIdx.x;
    int lane = tid & 31, wid = tid >> 5;
    int i = b * SCAN_B + tid;
    int v = (i < Nn) ? d_deg[i] : 0;

    // warp inclusive scan
    int x = v;
    #pragma unroll
    for (int off = 1; off < 32; off <<= 1) {
        int t = __shfl_up_sync(FULLM, x, off);
        if (lane >= off) x += t;
    }
    if (lane == 31) warpsum[wid] = x;
    __syncthreads();
    if (wid == 0) {
        int y = warpsum[lane];
        #pragma unroll
        for (int off = 1; off < 32; off <<= 1) {
            int t = __shfl_up_sync(FULLM, y, off);
            if (lane >= off) y += t;
        }
        warpsum[lane] = y;           // inclusive warp prefix
    }
    __syncthreads();
    int blocktotal = warpsum[31];
    int incl = x + (wid ? warpsum[wid - 1] : 0);

    if (tid == 0) {
        unsigned long long w0 = ((b == 0) ? (2ULL << 32) : (1ULL << 32))
                              | (unsigned long long)(unsigned)blocktotal;
        atomicExch(&g_scanstate[b], w0);
        int excl = 0;
        if (b > 0) {
            int j = b - 1;
            while (j >= 0) {
                unsigned long long s = atomicAdd(&g_scanstate[j], 0ULL);
                unsigned st = (unsigned)(s >> 32);
                if (st == 0) continue;          // predecessor not published yet
                excl += (int)(unsigned)(s & 0xFFFFFFFFULL);
                if (st == 2) break;
                j--;
            }
            atomicExch(&g_scanstate[b],
                       (2ULL << 32) | (unsigned long long)(unsigned)(excl + blocktotal));
        }
        s_base = excl;
    }
    __syncthreads();
    int base = s_base;
    if (i < Nn) {
        int rp = base + incl - v;                 // exclusive prefix
        float di = rsqrtf((float)d_deg[i] + 1.0f);
        d_rowptr[i] = rp;
        d_dinv[i] = di;
        NodeInfo ni; ni.rp = rp; ni.dinv = di;
        d_ninfo[i] = ni;
    }
}

// Scatter edges into CSR slots, 4 edges/thread — NO atomics.
// dst-side (rowptr,dinv) fused into one 8B NodeInfo load.
__global__ void k_scatter(const void* __restrict__ ei) {
    int is64 = g_is64;
    int t = blockIdx.x * blockDim.x + threadIdx.x;
    int e = t * 4;
    if (e >= Ee) return;
    int s0, s1, s2, s3, d0, d1, d2, d3;
    if (is64) {
        const longlong2* ps = (const longlong2*)ei;
        const longlong2* pd = (const longlong2*)((const long long*)ei + Ee);
        longlong2 a = ps[t * 2], b = ps[t * 2 + 1];
        longlong2 c = pd[t * 2], d = pd[t * 2 + 1];
        s0 = (int)a.x; s1 = (int)a.y; s2 = (int)b.x; s3 = (int)b.y;
        d0 = (int)c.x; d1 = (int)c.y; d2 = (int)d.x; d3 = (int)d.y;
    } else {
        int4 vs = ((const int4*)ei)[t];
        int4 vd = ((const int4*)((const int*)ei + Ee))[t];
        s0 = vs.x; s1 = vs.y; s2 = vs.z; s3 = vs.w;
        d0 = vd.x; d1 = vd.y; d2 = vd.z; d3 = vd.w;
    }
    int4 r = ((const int4*)d_rank)[t];
    NodeInfo n0 = d_ninfo[d0], n1 = d_ninfo[d1], n2 = d_ninfo[d2], n3 = d_ninfo[d3];
    EdgeW ew;
    ew.s = s0; ew.w = d_dinv[s0] * n0.dinv; d_edges[n0.rp + r.x] = ew;
    ew.s = s1; ew.w = d_dinv[s1] * n1.dinv; d_edges[n1.rp + r.y] = ew;
    ew.s = s2; ew.w = d_dinv[s2] * n2.dinv; d_edges[n2.rp + r.z] = ew;
    ew.s = s3; ew.w = d_dinv[s3] * n3.dinv; d_edges[n3.rp + r.w] = ew;
}

// ---------------------------------------------------------------------------
// GEMM1 via WMMA fp16 (HMMA), fp32 accumulate, fp16 epilogue.
#define GA_PITCH 136   // half, 272B = 17x16B -> conflict-free, 16B-mult ldm
#define GB_PITCH 72    // half, 144B = 9x16B
__global__ __launch_bounds__(256) void k_gemm1(const float* __restrict__ X,
                                               const float* __restrict__ W1) {
    __shared__ __align__(16) char sm[64 * GA_PITCH * 2 + 128 * GB_PITCH * 2];
    __half* sA = (__half*)sm;                              // [64][GA_PITCH]
    __half* sB = (__half*)(sm + 64 * GA_PITCH * 2);        // [128][GB_PITCH]
    float*  sC = (float*)sm;                               // [64][64] (reuse)

    int tid = threadIdx.x;
    int row0 = blockIdx.x * 64;

    #pragma unroll
    for (int it = 0; it < 8; it++) {
        int i4 = (it * 256 + tid) * 4;
        int r = i4 >> 7, c = i4 & 127;
        int row = row0 + r;
        float4 v = make_float4(0.f, 0.f, 0.f, 0.f);
        if (row < Nn) v = *(const float4*)&X[(size_t)row * 128 + c];
        __half2* dst = (__half2*)&sA[r * GA_PITCH + c];
        dst[0] = __floats2half2_rn(v.x, v.y);
        dst[1] = __floats2half2_rn(v.z, v.w);
    }
    #pragma unroll
    for (int it = 0; it < 8; it++) {
        int i4 = (it * 256 + tid) * 4;
        int k = i4 >> 6, c = i4 & 63;
        float4 v = *(const float4*)&W1[(size_t)k * 64 + c];
        __half2* dst = (__half2*)&sB[k * GB_PITCH + c];
        dst[0] = __floats2half2_rn(v.x, v.y);
        dst[1] = __floats2half2_rn(v.z, v.w);
    }
    __syncthreads();

    int wid = tid >> 5;
    int ct = wid & 3;
    int rp = wid >> 2;

    wmma::fragment<wmma::accumulator, 16, 16, 16, float> acc0, acc1;
    wmma::fill_fragment(acc0, 0.0f);
    wmma::fill_fragment(acc1, 0.0f);
    wmma::fragment<wmma::matrix_a, 16, 16, 16, __half, wmma::row_major> a0, a1;
    wmma::fragment<wmma::matrix_b, 16, 16, 16, __half, wmma::row_major> b;

    #pragma unroll
    for (int kt = 0; kt < 8; kt++) {
        wmma::load_matrix_sync(b, &sB[kt * 16 * GB_PITCH + ct * 16], GB_PITCH);
        wmma::load_matrix_sync(a0, &sA[(rp * 32 + 0) * GA_PITCH + kt * 16], GA_PITCH);
        wmma::load_matrix_sync(a1, &sA[(rp * 32 + 16) * GA_PITCH + kt * 16], GA_PITCH);
        wmma::mma_sync(acc0, a0, b, acc0);
        wmma::mma_sync(acc1, a1, b, acc1);
    }
    __syncthreads();

    wmma::store_matrix_sync(&sC[(rp * 32 + 0) * 64 + ct * 16], acc0, 64,
                            wmma::mem_row_major);
    wmma::store_matrix_sync(&sC[(rp * 32 + 16) * 64 + ct * 16], acc1, 64,
                            wmma::mem_row_major);
    __syncthreads();

    #pragma unroll
    for (int it = 0; it < 4; it++) {
        int i4 = (it * 256 + tid) * 4;
        int r = i4 >> 6, c = i4 & 63;
        int row = row0 + r;
        if (row < Nn) {
            float4 v = *(const float4*)&sC[r * 64 + c];
            __half2* dst = (__half2*)&d_h1[(size_t)row * 64 + c];
            dst[0] = __floats2half2_rn(v.x, v.y);
            dst[1] = __floats2half2_rn(v.z, v.w);
        }
    }
}

// Aggregation layer 1 (warp per node) + self-loop + bias + ReLU -> d_out1
__global__ __launch_bounds__(256) void k_agg1(const float* __restrict__ b1) {
    int warp = (blockIdx.x * blockDim.x + threadIdx.x) >> 5;
    int lane = threadIdx.x & 31;
    if (warp >= Nn) return;
    int n = warp;
    int start = d_rowptr[n];
    int end = start + d_deg[n];
    int half = lane >> 4;
    int sub  = lane & 15;
    const __half* __restrict__ h = d_h1;
    float a0 = 0.f, a1 = 0.f, a2 = 0.f, a3 = 0.f;

    for (int base = start; base < end; base += 32) {
        int rem = end - base; if (rem > 32) rem = 32;
        int s_l = 0; float w_l = 0.f;
        if (lane < rem) { EdgeW ew = d_edges[base + lane]; s_l = ew.s; w_l = ew.w; }
        int npair = (rem + 1) >> 1;
        for (int p = 0; p < npair; p++) {
            int idx = 2 * p + half;
            int   s = __shfl_sync(FULLM, s_l, idx);
            float w = __shfl_sync(FULLM, w_l, idx);
            if (idx < rem) {
                uint2 raw = *(const uint2*)(h + (size_t)s * 64 + sub * 4);
                float2 lo = __half22float2(*(__half2*)&raw.x);
                float2 hi = __half22float2(*(__half2*)&raw.y);
                a0 += lo.x * w; a1 += lo.y * w; a2 += hi.x * w; a3 += hi.y * w;
            }
        }
    }
    a0 += __shfl_xor_sync(FULLM, a0, 16);
    a1 += __shfl_xor_sync(FULLM, a1, 16);
    a2 += __shfl_xor_sync(FULLM, a2, 16);
    a3 += __shfl_xor_sync(FULLM, a3, 16);

    if (half == 0) {
        float di = d_dinv[n];
        float sl = di * di;
        uint2 raw = *(const uint2*)(h + (size_t)n * 64 + sub * 4);
        float2 lo = __half22float2(*(__half2*)&raw.x);
        float2 hi = __half22float2(*(__half2*)&raw.y);
        a0 += lo.x * sl; a1 += lo.y * sl; a2 += hi.x * sl; a3 += hi.y * sl;
        float4 bb = ((const float4*)b1)[sub];
        float4 o;
        o.x = fmaxf(a0 + bb.x, 0.f);
        o.y = fmaxf(a1 + bb.y, 0.f);
        o.z = fmaxf(a2 + bb.z, 0.f);
        o.w = fmaxf(a3 + bb.w, 0.f);
        ((float4*)d_out1)[(size_t)n * 16 + sub] = o;
    }
}

// GEMM2: h2[N,32] = out1[N,64] @ W2[64,32], epilogue stores fp16.
__global__ __launch_bounds__(256) void k_gemm2(const float* __restrict__ W2) {
    __shared__ float sW[64 * 32];
    __shared__ float sX[64 * 132];
    int tid = threadIdx.x;
    int row0 = blockIdx.x * 128;
    int cidx = tid & 7;
    int ridx = tid >> 3;
    float acc[4][4] = {};

    for (int i = tid; i < 64 * 32; i += 256) sW[i] = W2[i];
    for (int i = tid; i < 128 * 64; i += 256) {
        int r = i >> 6, k = i & 63;
        int row = row0 + r;
        sX[k * 132 + r] = (row < Nn) ? d_out1[(size_t)row * 64 + k] : 0.f;
    }
    __syncthreads();
    #pragma unroll
    for (int k = 0; k < 64; k++) {
        float4 w = *(const float4*)&sW[k * 32 + cidx * 4];
        float4 x = *(const float4*)&sX[k * 132 + ridx * 4];
        acc[0][0] += x.x * w.x; acc[0][1] += x.x * w.y; acc[0][2] += x.x * w.z; acc[0][3] += x.x * w.w;
        acc[1][0] += x.y * w.x; acc[1][1] += x.y * w.y; acc[1][2] += x.y * w.z; acc[1][3] += x.y * w.w;
        acc[2][0] += x.z * w.x; acc[2][1] += x.z * w.y; acc[2][2] += x.z * w.z; acc[2][3] += x.z * w.w;
        acc[3][0] += x.w * w.x; acc[3][1] += x.w * w.y; acc[3][2] += x.w * w.z; acc[3][3] += x.w * w.w;
    }
    #pragma unroll
    for (int rr = 0; rr < 4; rr++) {
        int row = row0 + ridx * 4 + rr;
        if (row < Nn) {
            __half2 p0 = __floats2half2_rn(acc[rr][0], acc[rr][1]);
            __half2 p1 = __floats2half2_rn(acc[rr][2], acc[rr][3]);
            __half2* dst = (__half2*)&d_h2[(size_t)row * 32 + cidx * 4];
            dst[0] = p0;
            dst[1] = p1;
        }
    }
}

// Aggregation layer 2 + bias + ReLU + classifier GEMV + log_softmax (warp/node)
__global__ __launch_bounds__(256) void k_final(const float* __restrict__ b2,
                                               const float* __restrict__ Wc,
                                               const float* __restrict__ bc,
                                               float* __restrict__ out) {
    __shared__ float sWc[32 * NC];
    __shared__ float sb2[32];
    __shared__ float sbc[16];
    int tid = threadIdx.x;
    for (int i = tid; i < 32 * NC; i += 256) sWc[i] = Wc[i];
    if (tid < 32) sb2[tid] = b2[tid];
    if (tid < NC) sbc[tid] = bc[tid];
    __syncthreads();

    int warp = (blockIdx.x * blockDim.x + tid) >> 5;
    int lane = tid & 31;
    if (warp >= Nn) return;
    int n = warp;
    int start = d_rowptr[n];
    int end = start + d_deg[n];
    int grp = lane >> 3;
    int sub = lane & 7;
    const __half* __restrict__ h = d_h2;
    float a0 = 0.f, a1 = 0.f, a2 = 0.f, a3 = 0.f;

    for (int base = start; base < end; base += 32) {
        int rem = end - base; if (rem > 32) rem = 32;
        int s_l = 0; float w_l = 0.f;
        if (lane < rem) { EdgeW ew = d_edges[base + lane]; s_l = ew.s; w_l = ew.w; }
        int ngrp = (rem + 3) >> 2;
        for (int p = 0; p < ngrp; p++) {
            int idx = 4 * p + grp;
            int   s = __shfl_sync(FULLM, s_l, idx);
            float w = __shfl_sync(FULLM, w_l, idx);
            if (idx < rem) {
                uint2 raw = *(const uint2*)(h + (size_t)s * 32 + sub * 4);
                float2 lo = __half22float2(*(__half2*)&raw.x);
                float2 hi = __half22float2(*(__half2*)&raw.y);
                a0 += lo.x * w; a1 += lo.y * w; a2 += hi.x * w; a3 += hi.y * w;
            }
        }
    }
    a0 += __shfl_xor_sync(FULLM, a0, 8);  a0 += __shfl_xor_sync(FULLM, a0, 16);
    a1 += __shfl_xor_sync(FULLM, a1, 8);  a1 += __shfl_xor_sync(FULLM, a1, 16);
    a2 += __shfl_xor_sync(FULLM, a2, 8);  a2 += __shfl_xor_sync(FULLM, a2, 16);
    a3 += __shfl_xor_sync(FULLM, a3, 8);  a3 += __shfl_xor_sync(FULLM, a3, 16);

    float di = d_dinv[n];
    float sl = di * di;
    uint2 raw = *(const uint2*)(h + (size_t)n * 32 + sub * 4);
    float2 lo = __half22float2(*(__half2*)&raw.x);
    float2 hi = __half22float2(*(__half2*)&raw.y);
    a0 += lo.x * sl; a1 += lo.y * sl; a2 += hi.x * sl; a3 += hi.y * sl;
    float v0 = fmaxf(a0 + sb2[sub * 4 + 0], 0.f);
    float v1 = fmaxf(a1 + sb2[sub * 4 + 1], 0.f);
    float v2 = fmaxf(a2 + sb2[sub * 4 + 2], 0.f);
    float v3 = fmaxf(a3 + sb2[sub * 4 + 3], 0.f);

    float p[NC];
    #pragma unroll
    for (int c = 0; c < NC; c++) {
        p[c] = v0 * sWc[(sub * 4 + 0) * NC + c]
             + v1 * sWc[(sub * 4 + 1) * NC + c]
             + v2 * sWc[(sub * 4 + 2) * NC + c]
             + v3 * sWc[(sub * 4 + 3) * NC + c];
    }
    #pragma unroll
    for (int off = 4; off >= 1; off >>= 1) {
        #pragma unroll
        for (int c = 0; c < NC; c++)
            p[c] += __shfl_xor_sync(FULLM, p[c], off);
    }
    if (lane == 0) {
        #pragma unroll
        for (int c = 0; c < NC; c++) p[c] += sbc[c];
        float m = p[0];
        #pragma unroll
        for (int c = 1; c < NC; c++) m = fmaxf(m, p[c]);
        float s = 0.f;
        #pragma unroll
        for (int c = 0; c < NC; c++) s += expf(p[c] - m);
        float lse = m + logf(s);
        #pragma unroll
        for (int c = 0; c < NC; c++)
            out[(size_t)n * NC + c] = p[c] - lse;
    }
}

// ---------------------------------------------------------------------------
extern "C" void kernel_launch(void* const* d_in, const int* in_sizes, int n_in,
                              void* d_out, int out_size) {
    const float* x  = (const float*)d_in[0];
    const void*  ei = d_in[1];
    const float* W1 = (const float*)d_in[2];
    const float* b1 = (const float*)d_in[3];
    const float* W2 = (const float*)d_in[4];
    const float* b2 = (const float*)d_in[5];
    const float* Wc = (const float*)d_in[6];
    const float* bc = (const float*)d_in[7];
    float* out = (float*)d_out;

    k_init<<<(Nn + 255) / 256, 256>>>((const int*)ei);      // 0
    k_deg<<<(Ee / 4 + 255) / 256, 256>>>(ei);               // 1
    k_scan<<<NB_SCAN, SCAN_B>>>();                          // 2 (lookback scan)
    k_scatter<<<(Ee / 4 + 255) / 256, 256>>>(ei);           // 3 <- ncu window
    k_gemm1<<<(Nn + 63) / 64, 256>>>(x, W1);                // 4
    k_agg1<<<(Nn + 7) / 8, 256>>>(b1);                      // 5
    k_gemm2<<<(Nn + 127) / 128, 256>>>(W2);                 // 6
    k_final<<<(Nn + 7) / 8, 256>>>(b2, Wc, bc, out);        // 7
}